// round 4
// baseline (speedup 1.0000x reference)
#include <cuda_runtime.h>
#include <cuda_bf16.h>

// Problem constants
#define B 4
#define P 12000
#define C 64
#define H 512
#define W 512
#define SLOT_CAP 48   // staged feature rows; overflow -> uniform slow path

// Winner pillar map per output pixel, encoded as (p+1); 0 = empty.
// Zero-initialized at module load; gather kernel restores it to 0
// (read-then-clear by the SAME thread), so the all-zeros invariant
// holds before every kernel_launch call / graph replay.
__device__ int g_winner[B * H * W];

// Kernel 1: one thread per (b, p). Reference semantics: sequential .at[].set
// means the LARGEST pillar index wins per pixel -> atomicMax on (p+1).
__global__ void scatter_winner_kernel(const int* __restrict__ coords) {
    int i = blockIdx.x * blockDim.x + threadIdx.x;   // i = b*P + p
    if (i >= B * P) return;
    int b = i / P;
    int p = i - b * P;
    int4 c4 = reinterpret_cast<const int4*>(coords)[i];  // (batch, y, x, z)
    int y = c4.y;
    int x = c4.z;
    if ((unsigned)x < (unsigned)W && (unsigned)y < (unsigned)H) {
        atomicMax(&g_winner[(b * H + y) * W + x], p + 1);
    }
}

// Kernel 2: one 128-thread block per (b, y) output row. 2048 blocks total,
// sized to be fully resident in ONE wave (~15 blocks/SM). Each thread owns
// one float4 x-position and streams all 64 channels with a 4xLDS + STG.128
// inner loop fed purely from shared memory (zero-row trick for empties).
__global__ __launch_bounds__(128, 15) void gather_out_kernel(
    const float* __restrict__ feat, float* __restrict__ out) {
    __shared__ int   s_slot[W];     // >=0: slot | -1: empty | <=-2: pid=-(s)-2
    __shared__ int   s_pid[SLOT_CAP];
    __shared__ int   s_n;
    __shared__ float s_feat[(SLOT_CAP + 1) * 65];  // +1 = zero row; pad 65

    const int y   = blockIdx.x;
    const int b   = blockIdx.y;
    const int tid = threadIdx.x;    // 0..127 == float4 x-position

    // --- Phase 1: read winner row (int4), clear it, build zero row.
    int4* wrow4 = reinterpret_cast<int4*>(g_winner + (b * H + y) * W);
    int4 w4 = wrow4[tid];
    if (tid == 0) s_n = 0;
    if (tid < 65) s_feat[SLOT_CAP * 65 + tid] = 0.0f;
    __syncthreads();

    wrow4[tid] = make_int4(0, 0, 0, 0);   // same thread as reader => ordered
    {
        const int wv[4] = {w4.x, w4.y, w4.z, w4.w};
        #pragma unroll
        for (int j = 0; j < 4; ++j) {
            int s = -1;
            if (wv[j] > 0) {
                int sl = atomicAdd(&s_n, 1);
                if (sl < SLOT_CAP) { s_pid[sl] = wv[j] - 1; s = sl; }
                else               { s = -(wv[j] + 1); }   // pid = -s - 2
            }
            s_slot[tid * 4 + j] = s;
        }
    }
    __syncthreads();

    // --- Phase 2: stage occupied feature rows into smem (coalesced float4).
    const float* featb = feat + (size_t)b * P * C;
    const float4* featb4 = reinterpret_cast<const float4*>(featb);
    const int n_stage = min(s_n, SLOT_CAP);
    for (int i = tid; i < n_stage * (C / 4); i += 128) {
        int sl = i >> 4;          // C/4 == 16
        int q  = i & 15;
        float4 v = __ldg(&featb4[(size_t)s_pid[sl] * (C / 4) + q]);
        float* dst = &s_feat[sl * 65 + q * 4];
        dst[0] = v.x; dst[1] = v.y; dst[2] = v.z; dst[3] = v.w;
    }
    __syncthreads();

    // --- Phase 3: emit all 64 channels for this thread's 4 pixels.
    const int s0 = s_slot[tid * 4 + 0];
    const int s1 = s_slot[tid * 4 + 1];
    const int s2 = s_slot[tid * 4 + 2];
    const int s3 = s_slot[tid * 4 + 3];

    float4* dst = reinterpret_cast<float4*>(out)
                + ((size_t)(b * C) * H + y) * (W / 4) + tid;
    const size_t step = (size_t)H * W / 4;   // one channel

    if (s_n <= SLOT_CAP) {
        // Fast path: remap empties to the zero row -> pure LDS + STG stream.
        const float* f0 = s_feat + (s0 >= 0 ? s0 : SLOT_CAP) * 65;
        const float* f1 = s_feat + (s1 >= 0 ? s1 : SLOT_CAP) * 65;
        const float* f2 = s_feat + (s2 >= 0 ? s2 : SLOT_CAP) * 65;
        const float* f3 = s_feat + (s3 >= 0 ? s3 : SLOT_CAP) * 65;
        #pragma unroll 8
        for (int c = 0; c < C; ++c) {
            float4 v = make_float4(f0[c], f1[c], f2[c], f3[c]);
            __stcs(dst, v);
            dst += step;
        }
    } else {
        // Rare slow path (row with >SLOT_CAP occupied pixels).
        #pragma unroll 4
        for (int c = 0; c < C; ++c) {
            float4 v;
            v.x = (s0 >= 0) ? s_feat[s0 * 65 + c]
                : (s0 == -1) ? 0.0f : featb[(size_t)(-s0 - 2) * C + c];
            v.y = (s1 >= 0) ? s_feat[s1 * 65 + c]
                : (s1 == -1) ? 0.0f : featb[(size_t)(-s1 - 2) * C + c];
            v.z = (s2 >= 0) ? s_feat[s2 * 65 + c]
                : (s2 == -1) ? 0.0f : featb[(size_t)(-s2 - 2) * C + c];
            v.w = (s3 >= 0) ? s_feat[s3 * 65 + c]
                : (s3 == -1) ? 0.0f : featb[(size_t)(-s3 - 2) * C + c];
            __stcs(dst, v);
            dst += step;
        }
    }
}

extern "C" void kernel_launch(void* const* d_in, const int* in_sizes, int n_in,
                              void* d_out, int out_size) {
    const float* feat   = (const float*)d_in[0];   // [B, P, C] fp32
    const int*   coords = (const int*)d_in[1];     // [B, P, 4] int32
    float* out = (float*)d_out;                    // [B, C, H, W] fp32

    scatter_winner_kernel<<<(B * P + 255) / 256, 256>>>(coords);

    dim3 grid(H, B);   // 2048 blocks, one per output row, single wave
    gather_out_kernel<<<grid, 128>>>(feat, out);
}

// round 5
// speedup vs baseline: 1.1248x; 1.1248x over previous
#include <cuda_runtime.h>
#include <cuda_bf16.h>

// Problem constants
#define B 4
#define P 12000
#define C 64
#define H 512
#define W 512
#define TILE_X 128
#define SLOT_CAP 20   // staged rows per 128-px tile (mean occ 5.9, +6 sigma)

// Winner pillar map per output pixel, encoded as (p+1); 0 = empty.
// Zero-initialized at module load; gather kernel restores its strip to 0
// (read-then-clear by the SAME thread => ordered), so the all-zeros
// invariant holds before every kernel_launch call / graph replay.
__device__ int g_winner[B * H * W];

// Kernel 1: one thread per (b, p). Reference semantics: sequential .at[].set
// means the LARGEST pillar index wins per pixel -> atomicMax on (p+1).
__global__ void scatter_winner_kernel(const int* __restrict__ coords) {
    int i = blockIdx.x * blockDim.x + threadIdx.x;   // i = b*P + p
    if (i >= B * P) return;
    int b = i / P;
    int p = i - b * P;
    int4 c4 = reinterpret_cast<const int4*>(coords)[i];  // (batch, y, x, z)
    int y = c4.y;
    int x = c4.z;
    if ((unsigned)x < (unsigned)W && (unsigned)y < (unsigned)H) {
        atomicMax(&g_winner[(b * H + y) * W + x], p + 1);
    }
}

// Kernel 2: one 128-thread block per (b, y, 128-px x-tile). 8192 blocks,
// ~16 resident/SM, ~3.5 waves -> prologues of late blocks overlap with the
// store streams of early ones (this pipelining is what R2 got right).
// Emit loop is select-free: empties remap to a shared zero row.
__global__ __launch_bounds__(128) void gather_out_kernel(
    const float* __restrict__ feat, float* __restrict__ out) {
    __shared__ int   s_slot[TILE_X];   // >=0: slot | -1: empty | <=-2: pid=-(s)-2
    __shared__ int   s_pid[SLOT_CAP];
    __shared__ int   s_n;
    __shared__ float s_feat[(SLOT_CAP + 1) * 65];  // +1 zero row; pad 65

    const int b   = blockIdx.z;
    const int y   = blockIdx.y;
    const int x0  = blockIdx.x * TILE_X;
    const int tid = threadIdx.x;

    // --- Phase 1: warp 0 reads + clears the 512-B winner strip and compacts.
    int4* wrow4 = reinterpret_cast<int4*>(g_winner + (b * H + y) * W + x0);
    int4 w4;
    if (tid < TILE_X / 4) w4 = wrow4[tid];
    if (tid == 0) s_n = 0;
    if (tid >= 63 && tid < 128) s_feat[SLOT_CAP * 65 + (tid - 63)] = 0.0f;
    __syncthreads();

    if (tid < TILE_X / 4) {
        wrow4[tid] = make_int4(0, 0, 0, 0);   // same thread as reader
        const int wv[4] = {w4.x, w4.y, w4.z, w4.w};
        #pragma unroll
        for (int j = 0; j < 4; ++j) {
            int s = -1;
            if (wv[j] > 0) {
                int sl = atomicAdd(&s_n, 1);
                if (sl < SLOT_CAP) { s_pid[sl] = wv[j] - 1; s = sl; }
                else               { s = -(wv[j] + 1); }   // pid = -s - 2
            }
            s_slot[tid * 4 + j] = s;
        }
    }
    __syncthreads();

    // --- Phase 2: stage occupied feature rows (coalesced float4 loads).
    const float* featb = feat + (size_t)b * P * C;
    const float4* featb4 = reinterpret_cast<const float4*>(featb);
    const int n_stage = min(s_n, SLOT_CAP);
    for (int i = tid; i < n_stage * (C / 4); i += 128) {
        int sl = i >> 4;          // C/4 == 16
        int q  = i & 15;
        float4 v = __ldg(&featb4[(size_t)s_pid[sl] * (C / 4) + q]);
        float* dst = &s_feat[sl * 65 + q * 4];
        dst[0] = v.x; dst[1] = v.y; dst[2] = v.z; dst[3] = v.w;
    }
    __syncthreads();

    // --- Phase 3: emit. lane = x-quad (32 quads), warp w = channels w+4*it.
    const int lane = tid & 31;
    const int c0   = tid >> 5;           // 0..3
    const int px   = lane * 4;

    const int s0 = s_slot[px + 0];
    const int s1 = s_slot[px + 1];
    const int s2 = s_slot[px + 2];
    const int s3 = s_slot[px + 3];

    float4* dst = reinterpret_cast<float4*>(out)
                + ((size_t)(b * C + c0) * H + y) * (W / 4) + (x0 / 4) + lane;
    const size_t step = (size_t)4 * H * (W / 4);   // c += 4

    if (s_n <= SLOT_CAP) {
        const float* f0 = s_feat + (s0 >= 0 ? s0 : SLOT_CAP) * 65;
        const float* f1 = s_feat + (s1 >= 0 ? s1 : SLOT_CAP) * 65;
        const float* f2 = s_feat + (s2 >= 0 ? s2 : SLOT_CAP) * 65;
        const float* f3 = s_feat + (s3 >= 0 ? s3 : SLOT_CAP) * 65;
        #pragma unroll 8
        for (int it = 0; it < 16; ++it) {
            const int c = c0 + 4 * it;
            float4 v = make_float4(f0[c], f1[c], f2[c], f3[c]);
            __stcs(dst, v);
            dst += step;
        }
    } else {
        // Statistically-never slow path (tile with >SLOT_CAP occupied px).
        #pragma unroll 4
        for (int it = 0; it < 16; ++it) {
            const int c = c0 + 4 * it;
            float4 v;
            v.x = (s0 >= 0) ? s_feat[s0 * 65 + c]
                : (s0 == -1) ? 0.0f : featb[(size_t)(-s0 - 2) * C + c];
            v.y = (s1 >= 0) ? s_feat[s1 * 65 + c]
                : (s1 == -1) ? 0.0f : featb[(size_t)(-s1 - 2) * C + c];
            v.z = (s2 >= 0) ? s_feat[s2 * 65 + c]
                : (s2 == -1) ? 0.0f : featb[(size_t)(-s2 - 2) * C + c];
            v.w = (s3 >= 0) ? s_feat[s3 * 65 + c]
                : (s3 == -1) ? 0.0f : featb[(size_t)(-s3 - 2) * C + c];
            __stcs(dst, v);
            dst += step;
        }
    }
}

extern "C" void kernel_launch(void* const* d_in, const int* in_sizes, int n_in,
                              void* d_out, int out_size) {
    const float* feat   = (const float*)d_in[0];   // [B, P, C] fp32
    const int*   coords = (const int*)d_in[1];     // [B, P, 4] int32
    float* out = (float*)d_out;                    // [B, C, H, W] fp32

    scatter_winner_kernel<<<(B * P + 255) / 256, 256>>>(coords);

    dim3 grid(W / TILE_X, H, B);   // 8192 blocks
    gather_out_kernel<<<grid, 128>>>(feat, out);
}